// round 3
// baseline (speedup 1.0000x reference)
#include <cuda_runtime.h>

// Problem shape (fixed)
#define BB 2
#define SS 2048
#define EE 1024
#define HH 16
#define DD 64
#define MTOT (BB*SS)   // 4096 rows of x / output

// Scratch (device globals; no allocation allowed in kernel_launch)
__device__ float g_q[BB*HH*SS*DD];     // [B,H,S,D]
__device__ float g_k[BB*HH*SS*DD];
__device__ float g_v[BB*HH*SS*DD];
__device__ float g_attn[BB*SS*HH*DD];  // [B,S,H*D]  (concat-ready)

// ---------------------------------------------------------------------------
// Kernel 1: QKV projection.  One block = 64 rows of x, one head, one of {q,k,v}.
// C[64x64] = X[64x1024] * W_h[1024x64] + bias.  4x4 micro-tiles, 256 threads.
// ---------------------------------------------------------------------------
__global__ __launch_bounds__(256) void proj_kernel(
    const float* __restrict__ x,
    const float* __restrict__ Wq, const float* __restrict__ Wk, const float* __restrict__ Wv,
    const float* __restrict__ bq, const float* __restrict__ bk, const float* __restrict__ bv)
{
    __shared__ float As[16][68];   // k-major A tile: As[kk][mm]
    __shared__ float Bs[16][68];   // k-major B tile: Bs[kk][nn]

    const int m0    = blockIdx.x * 64;
    const int h     = blockIdx.y;
    const int which = blockIdx.z;

    const float* W    = (which == 0) ? Wq : ((which == 1) ? Wk : Wv);
    const float* bias = (which == 0) ? bq : ((which == 1) ? bk : bv);
    float*       outp = (which == 0) ? g_q : ((which == 1) ? g_k : g_v);
    W += (size_t)h * EE * DD;

    const int tid = threadIdx.x;
    const int tx  = tid & 15;
    const int ty  = tid >> 4;

    float acc[4][4] = {};

    for (int k0 = 0; k0 < EE; k0 += 16) {
        #pragma unroll
        for (int i = 0; i < 4; i++) {
            int idx = tid + i * 256;
            int mm = idx >> 4, kk = idx & 15;
            As[kk][mm] = x[(size_t)(m0 + mm) * EE + k0 + kk];
        }
        #pragma unroll
        for (int i = 0; i < 4; i++) {
            int idx = tid + i * 256;
            int kk = idx >> 6, nn = idx & 63;
            Bs[kk][nn] = W[(size_t)(k0 + kk) * DD + nn];
        }
        __syncthreads();
        #pragma unroll
        for (int kk = 0; kk < 16; kk++) {
            float4 a4 = *(const float4*)&As[kk][ty * 4];
            float4 b4 = *(const float4*)&Bs[kk][tx * 4];
            float av[4] = {a4.x, a4.y, a4.z, a4.w};
            float bv4[4] = {b4.x, b4.y, b4.z, b4.w};
            #pragma unroll
            for (int i = 0; i < 4; i++)
                #pragma unroll
                for (int j = 0; j < 4; j++)
                    acc[i][j] += av[i] * bv4[j];
        }
        __syncthreads();
    }

    float4 bias4 = *(const float4*)&bias[h * DD + tx * 4];
    const float bb4[4] = {bias4.x, bias4.y, bias4.z, bias4.w};
    #pragma unroll
    for (int i = 0; i < 4; i++) {
        int rm = m0 + ty * 4 + i;
        int bidx = rm >> 11;       // / S
        int s    = rm & (SS - 1);
        float4 r;
        r.x = acc[i][0] + bb4[0];
        r.y = acc[i][1] + bb4[1];
        r.z = acc[i][2] + bb4[2];
        r.w = acc[i][3] + bb4[3];
        *(float4*)&outp[(((size_t)(bidx * HH + h)) * SS + s) * DD + tx * 4] = r;
    }
}

// ---------------------------------------------------------------------------
// Kernel 2: causal flash attention.  One block = 64 query rows of one (b,h).
// Online softmax; P tile overlaid into the K smem buffer (no S x S in memory).
// Dynamic smem: Qt[64][68] (k-major), KtP[64][68] (k-major K / row-major P),
// Vs[64][64] (natural).  51200 bytes.
// ---------------------------------------------------------------------------
__global__ __launch_bounds__(256) void attn_kernel()
{
    extern __shared__ float sm[];
    float* Qt  = sm;                // Qt[e*68 + r]
    float* KtP = sm + 64 * 68;      // Kt[e*68 + c]  /  Ps[r*68 + c]
    float* Vs  = sm + 2 * 64 * 68;  // Vs[c*64 + d]

    const int qt = gridDim.x - 1 - blockIdx.x;   // heavy tiles launch first
    const int h  = blockIdx.y;
    const int b  = blockIdx.z;

    const float* Q = g_q + ((size_t)(b * HH + h)) * SS * DD;
    const float* K = g_k + ((size_t)(b * HH + h)) * SS * DD;
    const float* V = g_v + ((size_t)(b * HH + h)) * SS * DD;

    const int tid = threadIdx.x;
    const int tx  = tid & 15;
    const int ty  = tid >> 4;

    // Load Q tile, transposed to k-major
    #pragma unroll
    for (int i = 0; i < 16; i++) {
        int idx = tid + i * 256;
        int r = idx >> 6, e = idx & 63;
        Qt[e * 68 + r] = Q[(size_t)(qt * 64 + r) * DD + e];
    }

    float o[4][4] = {};
    float mrow[4], lrow[4];
    #pragma unroll
    for (int i = 0; i < 4; i++) { mrow[i] = -1e30f; lrow[i] = 0.f; }

    for (int kt = 0; kt <= qt; kt++) {
        __syncthreads();   // previous iteration done with KtP/Vs (also orders Qt)
        #pragma unroll
        for (int i = 0; i < 16; i++) {
            int idx = tid + i * 256;
            int c = idx >> 6, e = idx & 63;
            KtP[e * 68 + c] = K[(size_t)(kt * 64 + c) * DD + e];
            Vs[c * 64 + e]  = V[(size_t)(kt * 64 + c) * DD + e];
        }
        __syncthreads();

        // S = Q K^T  (64x64x64), 4x4 per thread
        float s[4][4] = {};
        #pragma unroll
        for (int e = 0; e < 64; e++) {
            float4 a4 = *(const float4*)&Qt[e * 68 + ty * 4];
            float4 b4 = *(const float4*)&KtP[e * 68 + tx * 4];
            float av[4] = {a4.x, a4.y, a4.z, a4.w};
            float bv4[4] = {b4.x, b4.y, b4.z, b4.w};
            #pragma unroll
            for (int i = 0; i < 4; i++)
                #pragma unroll
                for (int j = 0; j < 4; j++)
                    s[i][j] += av[i] * bv4[j];
        }

        // scale + causal mask (only the diagonal tile needs masking)
        const bool diag = (kt == qt);
        #pragma unroll
        for (int i = 0; i < 4; i++)
            #pragma unroll
            for (int j = 0; j < 4; j++) {
                float sv = s[i][j] * 0.125f;   // 1/sqrt(64)
                if (diag && (tx * 4 + j > ty * 4 + i)) sv = -1e30f;
                s[i][j] = sv;
            }

        // online softmax update (16 lanes per query row; shfl over tx group)
        float f[4];
        #pragma unroll
        for (int i = 0; i < 4; i++) {
            float tm = fmaxf(fmaxf(s[i][0], s[i][1]), fmaxf(s[i][2], s[i][3]));
            #pragma unroll
            for (int off = 8; off >= 1; off >>= 1)
                tm = fmaxf(tm, __shfl_xor_sync(0xffffffffu, tm, off));
            float mn = fmaxf(mrow[i], tm);
            f[i] = __expf(mrow[i] - mn);
            mrow[i] = mn;
            float rs = 0.f;
            #pragma unroll
            for (int j = 0; j < 4; j++) { s[i][j] = __expf(s[i][j] - mn); rs += s[i][j]; }
            #pragma unroll
            for (int off = 8; off >= 1; off >>= 1)
                rs += __shfl_xor_sync(0xffffffffu, rs, off);
            lrow[i] = lrow[i] * f[i] + rs;
            #pragma unroll
            for (int j = 0; j < 4; j++) o[i][j] *= f[i];
        }

        __syncthreads();   // everyone done reading Kt before overlaying P
        #pragma unroll
        for (int i = 0; i < 4; i++) {
            float4 pv = make_float4(s[i][0], s[i][1], s[i][2], s[i][3]);
            *(float4*)&KtP[(ty * 4 + i) * 68 + tx * 4] = pv;
        }
        __syncthreads();

        // O += P V   (64x64x64), 4x4 per thread
        #pragma unroll
        for (int c = 0; c < 64; c++) {
            float4 v4 = *(const float4*)&Vs[c * 64 + tx * 4];
            float vj[4] = {v4.x, v4.y, v4.z, v4.w};
            float pw[4];
            #pragma unroll
            for (int i = 0; i < 4; i++) pw[i] = KtP[(ty * 4 + i) * 68 + c];
            #pragma unroll
            for (int i = 0; i < 4; i++)
                #pragma unroll
                for (int j = 0; j < 4; j++)
                    o[i][j] += pw[i] * vj[j];
        }
    }

    // epilogue: normalize and store concat-ready [B,S,H*D]
    #pragma unroll
    for (int i = 0; i < 4; i++) {
        int r = qt * 64 + ty * 4 + i;
        float invl = 1.0f / lrow[i];
        float4 rv = make_float4(o[i][0] * invl, o[i][1] * invl,
                                o[i][2] * invl, o[i][3] * invl);
        *(float4*)&g_attn[(((size_t)(b * SS + r)) * HH + h) * DD + tx * 4] = rv;
    }
}

// ---------------------------------------------------------------------------
// Kernel 3: output projection + bias + ReLU.
// out[4096,1024] = relu(g_attn[4096,1024] @ Wp[1024,1024] + bp)
// ---------------------------------------------------------------------------
__global__ __launch_bounds__(256) void out_kernel(
    const float* __restrict__ Wp, const float* __restrict__ bp,
    float* __restrict__ out)
{
    __shared__ float As[16][68];
    __shared__ float Bs[16][68];

    const int n0 = blockIdx.x * 64;
    const int m0 = blockIdx.y * 64;
    const int tid = threadIdx.x;
    const int tx  = tid & 15;
    const int ty  = tid >> 4;
    const int Kdim = HH * DD;  // 1024

    float acc[4][4] = {};

    for (int k0 = 0; k0 < Kdim; k0 += 16) {
        #pragma unroll
        for (int i = 0; i < 4; i++) {
            int idx = tid + i * 256;
            int mm = idx >> 4, kk = idx & 15;
            As[kk][mm] = g_attn[(size_t)(m0 + mm) * Kdim + k0 + kk];
        }
        #pragma unroll
        for (int i = 0; i < 4; i++) {
            int idx = tid + i * 256;
            int kk = idx >> 6, nn = idx & 63;
            Bs[kk][nn] = Wp[(size_t)(k0 + kk) * EE + n0 + nn];
        }
        __syncthreads();
        #pragma unroll
        for (int kk = 0; kk < 16; kk++) {
            float4 a4 = *(const float4*)&As[kk][ty * 4];
            float4 b4 = *(const float4*)&Bs[kk][tx * 4];
            float av[4] = {a4.x, a4.y, a4.z, a4.w};
            float bv4[4] = {b4.x, b4.y, b4.z, b4.w};
            #pragma unroll
            for (int i = 0; i < 4; i++)
                #pragma unroll
                for (int j = 0; j < 4; j++)
                    acc[i][j] += av[i] * bv4[j];
        }
        __syncthreads();
    }

    float4 bias4 = *(const float4*)&bp[n0 + tx * 4];
    const float bb4[4] = {bias4.x, bias4.y, bias4.z, bias4.w};
    #pragma unroll
    for (int i = 0; i < 4; i++) {
        float4 r;
        r.x = fmaxf(acc[i][0] + bb4[0], 0.f);
        r.y = fmaxf(acc[i][1] + bb4[1], 0.f);
        r.z = fmaxf(acc[i][2] + bb4[2], 0.f);
        r.w = fmaxf(acc[i][3] + bb4[3], 0.f);
        *(float4*)&out[(size_t)(m0 + ty * 4 + i) * EE + n0 + tx * 4] = r;
    }
}

// ---------------------------------------------------------------------------
extern "C" void kernel_launch(void* const* d_in, const int* in_sizes, int n_in,
                              void* d_out, int out_size)
{
    const float* x  = (const float*)d_in[0];
    const float* Wq = (const float*)d_in[1];
    const float* Wk = (const float*)d_in[2];
    const float* Wv = (const float*)d_in[3];
    const float* bq = (const float*)d_in[4];
    const float* bk = (const float*)d_in[5];
    const float* bv = (const float*)d_in[6];
    const float* Wp = (const float*)d_in[7];
    const float* bp = (const float*)d_in[8];
    float* out = (float*)d_out;

    (void)in_sizes; (void)n_in; (void)out_size;

    // 51200 B dynamic smem > 48 KB default; attribute call is not a stream op
    // (capture-safe), idempotent, called every launch.
    cudaFuncSetAttribute(attn_kernel,
                         cudaFuncAttributeMaxDynamicSharedMemorySize, 51200);

    dim3 gp(MTOT / 64, HH, 3);
    proj_kernel<<<gp, 256>>>(x, Wq, Wk, Wv, bq, bk, bv);

    dim3 ga(SS / 64, HH, BB);
    attn_kernel<<<ga, 256, 51200>>>();

    dim3 go(EE / 64, MTOT / 64);
    out_kernel<<<go, 256>>>(Wp, bp, out);
}

// round 4
// speedup vs baseline: 1.0754x; 1.0754x over previous
#include <cuda_runtime.h>

// Problem shape (fixed)
#define BB 2
#define SS 2048
#define EE 1024
#define HH 16
#define DD 64
#define MTOT (BB*SS)   // 4096

// Scratch (device globals)
__device__ float g_q[BB*HH*SS*DD];     // [B,H,S,D]
__device__ float g_k[BB*HH*SS*DD];
__device__ float g_v[BB*HH*SS*DD];
__device__ float g_attn[BB*SS*HH*DD];  // [B,S,H*D] (concat-ready)

// ---------------------------------------------------------------------------
// Kernel 1: fused QKV projection as one GEMM C[4096, 3072].
// Columns: n -> which = n/1024, h = (n%1024)/64, d = n%64.
// 128x128 block tile, 8x8 micro-tile, K-step 8, register prefetch.
// ---------------------------------------------------------------------------
__global__ __launch_bounds__(256) void proj_kernel(
    const float* __restrict__ x,
    const float* __restrict__ Wq, const float* __restrict__ Wk, const float* __restrict__ Wv,
    const float* __restrict__ bq, const float* __restrict__ bk, const float* __restrict__ bv)
{
    __shared__ float As[8][132];   // As[kk][mm]
    __shared__ float Bs[8][132];   // Bs[kk][nn]

    const int n0 = blockIdx.x * 128;
    const int m0 = blockIdx.y * 128;

    const int which = n0 >> 10;                 // constant per block
    const float* W    = (which == 0) ? Wq : ((which == 1) ? Wk : Wv);
    const float* bias = (which == 0) ? bq : ((which == 1) ? bk : bv);
    float*       outp = (which == 0) ? g_q : ((which == 1) ? g_k : g_v);
    const int h0 = (n0 & 1023) >> 6;            // block spans heads h0, h0+1

    const int tid = threadIdx.x;
    const int tx  = tid & 15;
    const int ty  = tid >> 4;

    // per-thread load coords
    const int a_mm = tid >> 3, a_kk = tid & 7;      // + ii*32 rows
    const int b_nn = tid & 127, b_kk = tid >> 7;    // + ii*2 kk
    const int b_h  = h0 + (b_nn >> 6);
    const int b_d  = b_nn & 63;
    const size_t bBase = (size_t)b_h * EE * DD + b_d;

    float acc[8][8] = {};

    // prologue: first tile
    #pragma unroll
    for (int ii = 0; ii < 4; ii++)
        As[a_kk][a_mm + ii * 32] = x[(size_t)(m0 + a_mm + ii * 32) * EE + a_kk];
    #pragma unroll
    for (int ii = 0; ii < 4; ii++)
        Bs[b_kk + ii * 2][b_nn] = W[bBase + (size_t)(b_kk + ii * 2) * DD];
    __syncthreads();

    for (int k0 = 0; k0 < EE; k0 += 8) {
        float pa[4], pb[4];
        const bool more = (k0 + 8) < EE;
        if (more) {
            #pragma unroll
            for (int ii = 0; ii < 4; ii++)
                pa[ii] = x[(size_t)(m0 + a_mm + ii * 32) * EE + k0 + 8 + a_kk];
            #pragma unroll
            for (int ii = 0; ii < 4; ii++)
                pb[ii] = W[bBase + (size_t)(k0 + 8 + b_kk + ii * 2) * DD];
        }
        #pragma unroll
        for (int kk = 0; kk < 8; kk++) {
            float a[8], b[8];
            *(float4*)&a[0] = *(const float4*)&As[kk][ty * 4];
            *(float4*)&a[4] = *(const float4*)&As[kk][64 + ty * 4];
            *(float4*)&b[0] = *(const float4*)&Bs[kk][tx * 4];
            *(float4*)&b[4] = *(const float4*)&Bs[kk][64 + tx * 4];
            #pragma unroll
            for (int i = 0; i < 8; i++)
                #pragma unroll
                for (int j = 0; j < 8; j++)
                    acc[i][j] += a[i] * b[j];
        }
        __syncthreads();
        if (more) {
            #pragma unroll
            for (int ii = 0; ii < 4; ii++) As[a_kk][a_mm + ii * 32] = pa[ii];
            #pragma unroll
            for (int ii = 0; ii < 4; ii++) Bs[b_kk + ii * 2][b_nn] = pb[ii];
        }
        __syncthreads();
    }

    // epilogue: bias + scatter to [B,H,S,D]
    float4 bias4[2];
    bias4[0] = *(const float4*)&bias[(h0 + 0) * DD + tx * 4];
    bias4[1] = *(const float4*)&bias[(h0 + 1) * DD + tx * 4];
    #pragma unroll
    for (int i = 0; i < 8; i++) {
        int r  = ty * 4 + (i & 3) + ((i >> 2) * 64);
        int rm = m0 + r;
        int bi = rm >> 11;
        int s  = rm & (SS - 1);
        #pragma unroll
        for (int g = 0; g < 2; g++) {
            const float* bb = (const float*)&bias4[g];
            float4 rv;
            rv.x = acc[i][g * 4 + 0] + bb[0];
            rv.y = acc[i][g * 4 + 1] + bb[1];
            rv.z = acc[i][g * 4 + 2] + bb[2];
            rv.w = acc[i][g * 4 + 3] + bb[3];
            int h = h0 + g;
            *(float4*)&outp[(((size_t)(bi * HH + h)) * SS + s) * DD + tx * 4] = rv;
        }
    }
}

// ---------------------------------------------------------------------------
// Kernel 2: causal flash attention. One block = 128 query rows of one (b,h).
// 128x128 S tiles, 8x8 micro; O is 8x4 (D=64). P overlaid onto Kt buffer.
// smem (floats): Qt[64][132] | KtPs (Kt[64][132] / Ps[128][132]) | Vs[128][68]
// = 8448 + 16896 + 8704 = 34048 floats = 136192 bytes.
// ---------------------------------------------------------------------------
__global__ __launch_bounds__(256) void attn_kernel()
{
    extern __shared__ float sm[];
    float* Qt   = sm;                    // Qt[e*132 + r]
    float* KtPs = sm + 64 * 132;         // Kt[e*132 + c] / Ps[r*132 + c]
    float* Vs   = sm + 64 * 132 + 128 * 132;  // Vs[c*68 + d]

    const int qt = gridDim.x - 1 - blockIdx.x;   // heavy tiles first
    const int h  = blockIdx.y;
    const int b  = blockIdx.z;
    const int q0 = qt * 128;

    const float* Q = g_q + ((size_t)(b * HH + h)) * SS * DD;
    const float* K = g_k + ((size_t)(b * HH + h)) * SS * DD;
    const float* V = g_v + ((size_t)(b * HH + h)) * SS * DD;

    const int tid = threadIdx.x;
    const int tx  = tid & 15;
    const int ty  = tid >> 4;

    // Load Q tile transposed (d-major): 8192 elems, 32/thread
    #pragma unroll
    for (int ii = 0; ii < 32; ii++) {
        int idx = tid + ii * 256;
        int r = idx >> 6, e = idx & 63;
        Qt[e * 132 + r] = Q[(size_t)(q0 + r) * DD + e];
    }

    float o[8][4] = {};
    float mrow[8], lrow[8];
    #pragma unroll
    for (int i = 0; i < 8; i++) { mrow[i] = -1e30f; lrow[i] = 0.f; }

    int rbase[8];
    #pragma unroll
    for (int i = 0; i < 8; i++)
        rbase[i] = (ty * 4 + (i & 3) + ((i >> 2) * 64)) * 132;

    for (int kt = 0; kt <= qt; kt++) {
        __syncthreads();   // prev iter done reading KtPs/Vs (and Qt stores on iter 0)
        #pragma unroll
        for (int ii = 0; ii < 32; ii++) {
            int idx = tid + ii * 256;
            int c = idx >> 6, e = idx & 63;
            float kv = K[(size_t)(kt * 128 + c) * DD + e];
            float vv = V[(size_t)(kt * 128 + c) * DD + e];
            KtPs[e * 132 + c] = kv;
            Vs[c * 68 + e]    = vv;
        }
        __syncthreads();

        // S = Q K^T  (128x128x64), 8x8 per thread
        float s[8][8] = {};
        #pragma unroll
        for (int e = 0; e < 64; e++) {
            float a[8], bb[8];
            *(float4*)&a[0]  = *(const float4*)&Qt[e * 132 + ty * 4];
            *(float4*)&a[4]  = *(const float4*)&Qt[e * 132 + 64 + ty * 4];
            *(float4*)&bb[0] = *(const float4*)&KtPs[e * 132 + tx * 4];
            *(float4*)&bb[4] = *(const float4*)&KtPs[e * 132 + 64 + tx * 4];
            #pragma unroll
            for (int i = 0; i < 8; i++)
                #pragma unroll
                for (int j = 0; j < 8; j++)
                    s[i][j] += a[i] * bb[j];
        }

        // scale + causal mask (diag tile only; tiles are square so local compare)
        const bool diag = (kt == qt);
        #pragma unroll
        for (int i = 0; i < 8; i++) {
            int r = ty * 4 + (i & 3) + ((i >> 2) * 64);
            #pragma unroll
            for (int j = 0; j < 8; j++) {
                int c = tx * 4 + (j & 3) + ((j >> 2) * 64);
                float sv = s[i][j] * 0.125f;
                if (diag && c > r) sv = -1e30f;
                s[i][j] = sv;
            }
        }

        // online softmax (16 lanes per row group)
        #pragma unroll
        for (int i = 0; i < 8; i++) {
            float tm = s[i][0];
            #pragma unroll
            for (int j = 1; j < 8; j++) tm = fmaxf(tm, s[i][j]);
            #pragma unroll
            for (int off = 8; off >= 1; off >>= 1)
                tm = fmaxf(tm, __shfl_xor_sync(0xffffffffu, tm, off));
            float mn = fmaxf(mrow[i], tm);
            float f  = __expf(mrow[i] - mn);
            mrow[i] = mn;
            float rs = 0.f;
            #pragma unroll
            for (int j = 0; j < 8; j++) { s[i][j] = __expf(s[i][j] - mn); rs += s[i][j]; }
            #pragma unroll
            for (int off = 8; off >= 1; off >>= 1)
                rs += __shfl_xor_sync(0xffffffffu, rs, off);
            lrow[i] = lrow[i] * f + rs;
            #pragma unroll
            for (int j = 0; j < 4; j++) o[i][j] *= f;
        }

        __syncthreads();   // done reading Kt before overlaying P
        #pragma unroll
        for (int i = 0; i < 8; i++) {
            *(float4*)&KtPs[rbase[i] + tx * 4]      = *(float4*)&s[i][0];
            *(float4*)&KtPs[rbase[i] + 64 + tx * 4] = *(float4*)&s[i][4];
        }
        __syncthreads();

        // O += P V  (128x64x128), 8x4 per thread, c unrolled by 4
        #pragma unroll 4
        for (int c = 0; c < 128; c += 4) {
            float4 p[8];
            #pragma unroll
            for (int i = 0; i < 8; i++)
                p[i] = *(const float4*)&KtPs[rbase[i] + c];
            #pragma unroll
            for (int cc = 0; cc < 4; cc++) {
                float4 v4 = *(const float4*)&Vs[(c + cc) * 68 + tx * 4];
                #pragma unroll
                for (int i = 0; i < 8; i++) {
                    float pv = ((const float*)&p[i])[cc];
                    o[i][0] += pv * v4.x;
                    o[i][1] += pv * v4.y;
                    o[i][2] += pv * v4.z;
                    o[i][3] += pv * v4.w;
                }
            }
        }
    }

    // epilogue: normalize, store concat-ready [B,S,H*D]
    #pragma unroll
    for (int i = 0; i < 8; i++) {
        int r = q0 + ty * 4 + (i & 3) + ((i >> 2) * 64);
        float invl = 1.0f / lrow[i];
        float4 rv = make_float4(o[i][0] * invl, o[i][1] * invl,
                                o[i][2] * invl, o[i][3] * invl);
        *(float4*)&g_attn[(((size_t)(b * SS + r)) * HH + h) * DD + tx * 4] = rv;
    }
}

// ---------------------------------------------------------------------------
// Kernel 3: output projection + bias + ReLU.  128x128x8, 8x8 micro.
// out[4096,1024] = relu(g_attn @ Wp + bp)
// ---------------------------------------------------------------------------
__global__ __launch_bounds__(256) void out_kernel(
    const float* __restrict__ Wp, const float* __restrict__ bp,
    float* __restrict__ out)
{
    __shared__ float As[8][132];
    __shared__ float Bs[8][132];

    const int n0 = blockIdx.x * 128;
    const int m0 = blockIdx.y * 128;
    const int tid = threadIdx.x;
    const int tx  = tid & 15;
    const int ty  = tid >> 4;

    const int a_mm = tid >> 3, a_kk = tid & 7;
    const int b_nn = tid & 127, b_kk = tid >> 7;

    float acc[8][8] = {};

    #pragma unroll
    for (int ii = 0; ii < 4; ii++)
        As[a_kk][a_mm + ii * 32] = g_attn[(size_t)(m0 + a_mm + ii * 32) * EE + a_kk];
    #pragma unroll
    for (int ii = 0; ii < 4; ii++)
        Bs[b_kk + ii * 2][b_nn] = Wp[(size_t)(b_kk + ii * 2) * EE + n0 + b_nn];
    __syncthreads();

    for (int k0 = 0; k0 < EE; k0 += 8) {
        float pa[4], pb[4];
        const bool more = (k0 + 8) < EE;
        if (more) {
            #pragma unroll
            for (int ii = 0; ii < 4; ii++)
                pa[ii] = g_attn[(size_t)(m0 + a_mm + ii * 32) * EE + k0 + 8 + a_kk];
            #pragma unroll
            for (int ii = 0; ii < 4; ii++)
                pb[ii] = Wp[(size_t)(k0 + 8 + b_kk + ii * 2) * EE + n0 + b_nn];
        }
        #pragma unroll
        for (int kk = 0; kk < 8; kk++) {
            float a[8], b[8];
            *(float4*)&a[0] = *(const float4*)&As[kk][ty * 4];
            *(float4*)&a[4] = *(const float4*)&As[kk][64 + ty * 4];
            *(float4*)&b[0] = *(const float4*)&Bs[kk][tx * 4];
            *(float4*)&b[4] = *(const float4*)&Bs[kk][64 + tx * 4];
            #pragma unroll
            for (int i = 0; i < 8; i++)
                #pragma unroll
                for (int j = 0; j < 8; j++)
                    acc[i][j] += a[i] * b[j];
        }
        __syncthreads();
        if (more) {
            #pragma unroll
            for (int ii = 0; ii < 4; ii++) As[a_kk][a_mm + ii * 32] = pa[ii];
            #pragma unroll
            for (int ii = 0; ii < 4; ii++) Bs[b_kk + ii * 2][b_nn] = pb[ii];
        }
        __syncthreads();
    }

    float4 bias4[2];
    bias4[0] = *(const float4*)&bp[n0 + tx * 4];
    bias4[1] = *(const float4*)&bp[n0 + 64 + tx * 4];
    #pragma unroll
    for (int i = 0; i < 8; i++) {
        int r = m0 + ty * 4 + (i & 3) + ((i >> 2) * 64);
        #pragma unroll
        for (int g = 0; g < 2; g++) {
            const float* bb = (const float*)&bias4[g];
            float4 rv;
            rv.x = fmaxf(acc[i][g * 4 + 0] + bb[0], 0.f);
            rv.y = fmaxf(acc[i][g * 4 + 1] + bb[1], 0.f);
            rv.z = fmaxf(acc[i][g * 4 + 2] + bb[2], 0.f);
            rv.w = fmaxf(acc[i][g * 4 + 3] + bb[3], 0.f);
            *(float4*)&out[(size_t)r * EE + n0 + g * 64 + tx * 4] = rv;
        }
    }
}

// ---------------------------------------------------------------------------
extern "C" void kernel_launch(void* const* d_in, const int* in_sizes, int n_in,
                              void* d_out, int out_size)
{
    const float* x  = (const float*)d_in[0];
    const float* Wq = (const float*)d_in[1];
    const float* Wk = (const float*)d_in[2];
    const float* Wv = (const float*)d_in[3];
    const float* bq = (const float*)d_in[4];
    const float* bk = (const float*)d_in[5];
    const float* bv = (const float*)d_in[6];
    const float* Wp = (const float*)d_in[7];
    const float* bp = (const float*)d_in[8];
    float* out = (float*)d_out;

    (void)in_sizes; (void)n_in; (void)out_size;

    cudaFuncSetAttribute(attn_kernel,
                         cudaFuncAttributeMaxDynamicSharedMemorySize, 136192);

    dim3 gp(3 * EE / 128, MTOT / 128);   // 24 x 32
    proj_kernel<<<gp, 256>>>(x, Wq, Wk, Wv, bq, bk, bv);

    dim3 ga(SS / 128, HH, BB);           // 16 x 16 x 2
    attn_kernel<<<ga, 256, 136192>>>();

    dim3 go(EE / 128, MTOT / 128);       // 8 x 32
    out_kernel<<<go, 256>>>(Wp, bp, out);
}

// round 6
// speedup vs baseline: 1.6884x; 1.5700x over previous
#include <cuda_runtime.h>
#include <cstdint>

// Problem shape (fixed)
#define BB 2
#define SS 2048
#define EE 1024
#define HH 16
#define DD 64
#define MTOT (BB*SS)   // 4096

// Scratch (device globals)
__device__ float g_xr[MTOT*EE];        // x rounded to tf32 grid
__device__ float g_wt[3*EE*EE];        // W{q,k,v}^T: [which][n=h*64+d][e], rna-rounded
__device__ float g_wpt[EE*EE];         // Wp^T: [n][k], rna-rounded
__device__ float g_q[BB*HH*SS*DD];     // [B,H,S,D]
__device__ float g_k[BB*HH*SS*DD];
__device__ float g_v[BB*HH*SS*DD];
__device__ float g_attn[BB*SS*HH*DD];  // [B,S,H*D], rna-rounded

// ============================ helpers ============================
__device__ __forceinline__ uint32_t smem_to_u32(const void* p) {
    uint32_t a;
    asm("{ .reg .u64 t; cvta.to.shared.u64 t, %1; cvt.u32.u64 %0, t; }" : "=r"(a) : "l"(p));
    return a;
}
__device__ __forceinline__ float rna_tf32(float v) {
    float r; asm("cvt.rna.tf32.f32 %0, %1;" : "=f"(r) : "f"(v)); return r;
}
__device__ __forceinline__ void ldgsts16(uint32_t s, const float* g) {
    asm volatile("cp.async.cg.shared.global [%0], [%1], 16;" :: "r"(s), "l"(g) : "memory");
}
#define CP_COMMIT() asm volatile("cp.async.commit_group;" ::: "memory")
#define CP_WAIT2()  asm volatile("cp.async.wait_group 2;" ::: "memory")

// m16n8k8 tf32 mma: D += A*B  (A row-major m16k8, B col-major k8n8)
__device__ __forceinline__ void mma16n8k8(float* d, const uint32_t* a, const uint32_t* b) {
    asm volatile(
        "mma.sync.aligned.m16n8k8.row.col.f32.tf32.tf32.f32 "
        "{%0,%1,%2,%3}, {%4,%5,%6,%7}, {%8,%9}, {%0,%1,%2,%3};\n"
        : "+f"(d[0]), "+f"(d[1]), "+f"(d[2]), "+f"(d[3])
        : "r"(a[0]), "r"(a[1]), "r"(a[2]), "r"(a[3]), "r"(b[0]), "r"(b[1]));
}

// ============================ prep kernels ============================
__global__ __launch_bounds__(256) void round_x_kernel(const float* __restrict__ x)
{
    int i = blockIdx.x * blockDim.x + threadIdx.x;
    const int n4 = MTOT * EE / 4;
    for (; i < n4; i += gridDim.x * blockDim.x) {
        float4 v = ((const float4*)x)[i];
        v.x = rna_tf32(v.x); v.y = rna_tf32(v.y);
        v.z = rna_tf32(v.z); v.w = rna_tf32(v.w);
        ((float4*)g_xr)[i] = v;
    }
}

__global__ __launch_bounds__(256) void transpose_w_kernel(
    const float* __restrict__ Wq, const float* __restrict__ Wk, const float* __restrict__ Wv)
{
    __shared__ float t[32][33];
    const int zc = blockIdx.z;              // 0..47
    const int which = zc >> 4, h = zc & 15;
    const float* W = ((which == 0) ? Wq : (which == 1) ? Wk : Wv) + (size_t)h * EE * DD;
    const int e0 = blockIdx.x * 32, d0 = blockIdx.y * 32;
    const int tx = threadIdx.x & 31, ty8 = threadIdx.x >> 5;
    #pragma unroll
    for (int i = 0; i < 4; i++) {
        int e = ty8 + i * 8;
        t[e][tx] = rna_tf32(W[(size_t)(e0 + e) * DD + d0 + tx]);
    }
    __syncthreads();
    float* dst = g_wt + (size_t)which * EE * EE;
    #pragma unroll
    for (int i = 0; i < 4; i++) {
        int dr = ty8 + i * 8;
        dst[(size_t)(h * DD + d0 + dr) * EE + e0 + tx] = t[tx][dr];
    }
}

__global__ __launch_bounds__(256) void transpose_wp_kernel(const float* __restrict__ Wp)
{
    __shared__ float t[32][33];
    const int k0 = blockIdx.x * 32, n0 = blockIdx.y * 32;
    const int tx = threadIdx.x & 31, ty8 = threadIdx.x >> 5;
    #pragma unroll
    for (int i = 0; i < 4; i++) {
        int k = ty8 + i * 8;
        t[k][tx] = rna_tf32(Wp[(size_t)(k0 + k) * EE + n0 + tx]);
    }
    __syncthreads();
    #pragma unroll
    for (int i = 0; i < 4; i++) {
        int nr = ty8 + i * 8;
        g_wpt[(size_t)(n0 + nr) * EE + k0 + tx] = t[tx][nr];
    }
}

// ============================ mma.sync GEMM core ============================
// C[128x128] tile = A[m0.., K=1024] @ Bt[n0.., K=1024]^T, tf32 fragments.
// 256 threads = 8 warps: warp (wm = wid&3) rows wm*32..+32, (wn = wid>>2) cols wn*64..+64.
// Smem: 3 stages x (A 128x20 + B 128x20) floats, pitch 20 => conflict-free frag loads.
#define PITCH   20
#define STAGE_F (2*128*PITCH)   // 5120 floats per stage
#define GSMEM_BYTES (3*STAGE_F*4)  // 61440

__device__ __forceinline__ void gemm_load_stage(
    uint32_t smem_u32, int s, const float* __restrict__ Ag, const float* __restrict__ Bg,
    int m0, int n0, int kt, int tid)
{
    const uint32_t baseA = smem_u32 + s * (STAGE_F * 4);
    const uint32_t baseB = baseA + 128 * PITCH * 4;
    #pragma unroll
    for (int i = 0; i < 2; i++) {
        int cid = tid + i * 256;
        int r = cid >> 2, c = cid & 3;
        ldgsts16(baseA + (r * PITCH + c * 4) * 4, Ag + (size_t)(m0 + r) * EE + kt * 16 + c * 4);
        ldgsts16(baseB + (r * PITCH + c * 4) * 4, Bg + (size_t)(n0 + r) * EE + kt * 16 + c * 4);
    }
    CP_COMMIT();
}

__device__ __forceinline__ void gemm_mainloop_mma(
    const float* __restrict__ Ag, const float* __restrict__ Bg,
    int m0, int n0, float acc[2][8][4], float* __restrict__ sm)
{
    const int tid  = threadIdx.x;
    const int lane = tid & 31, wid = tid >> 5;
    const int g = lane >> 2, t4 = lane & 3;
    const int wm = wid & 3, wn = wid >> 2;
    const uint32_t smem_u32 = smem_to_u32(sm);

    gemm_load_stage(smem_u32, 0, Ag, Bg, m0, n0, 0, tid);
    gemm_load_stage(smem_u32, 1, Ag, Bg, m0, n0, 1, tid);

    const int KT = EE / 16;   // 64
    for (int t = 0; t < KT; t++) {
        const int s = t % 3;
        if (t + 2 < KT) gemm_load_stage(smem_u32, (t + 2) % 3, Ag, Bg, m0, n0, t + 2, tid);
        else            CP_COMMIT();
        CP_WAIT2();
        __syncthreads();

        const float* As = sm + s * STAGE_F;
        const float* Bs = As + 128 * PITCH;
        #pragma unroll
        for (int ks = 0; ks < 16; ks += 8) {
            uint32_t af[2][4], bf[8][2];
            #pragma unroll
            for (int mt = 0; mt < 2; mt++) {
                const int r = wm * 32 + mt * 16 + g;
                af[mt][0] = __float_as_uint(As[r * PITCH + ks + t4]);
                af[mt][1] = __float_as_uint(As[(r + 8) * PITCH + ks + t4]);
                af[mt][2] = __float_as_uint(As[r * PITCH + ks + t4 + 4]);
                af[mt][3] = __float_as_uint(As[(r + 8) * PITCH + ks + t4 + 4]);
            }
            #pragma unroll
            for (int nt = 0; nt < 8; nt++) {
                const int n = wn * 64 + nt * 8 + g;
                bf[nt][0] = __float_as_uint(Bs[n * PITCH + ks + t4]);
                bf[nt][1] = __float_as_uint(Bs[n * PITCH + ks + t4 + 4]);
            }
            #pragma unroll
            for (int mt = 0; mt < 2; mt++)
                #pragma unroll
                for (int nt = 0; nt < 8; nt++)
                    mma16n8k8(acc[mt][nt], af[mt], bf[nt]);
        }
        __syncthreads();
    }
}

// ---------------------------------------------------------------------------
// QKV projection: C[4096,3072] = Xr @ Wt^T; scatter + bias into g_q/g_k/g_v.
// ---------------------------------------------------------------------------
__global__ __launch_bounds__(256) void gemm_proj_kernel(
    const float* __restrict__ bq, const float* __restrict__ bk, const float* __restrict__ bv)
{
    extern __shared__ __align__(16) float sm[];
    const int n0 = blockIdx.x * 128;
    const int m0 = blockIdx.y * 128;

    float acc[2][8][4] = {};
    gemm_mainloop_mma(g_xr, g_wt + (size_t)n0 * EE - 0, m0, 0, acc, sm);
    // note: Bg indexed with row (n0 + r); pass Bg = g_wt and n0 directly instead:
    // (handled below by recomputing — see launch: we pass n0 via blockIdx)

    const int which = n0 >> 10;
    const int h0 = (n0 & 1023) >> 6;
    const float* bias = (which == 0) ? bq : (which == 1) ? bk : bv;
    float*       outp = (which == 0) ? g_q : (which == 1) ? g_k : g_v;

    const int lane = threadIdx.x & 31, wid = threadIdx.x >> 5;
    const int g = lane >> 2, t4 = lane & 3;
    const int wm = wid & 3, wn = wid >> 2;
    const int hh = h0 + wn;

    #pragma unroll
    for (int mt = 0; mt < 2; mt++) {
        #pragma unroll
        for (int half = 0; half < 2; half++) {
            const int row = m0 + wm * 32 + mt * 16 + g + half * 8;
            const int bi = row >> 11, sidx = row & (SS - 1);
            float* dst = &outp[(((size_t)(bi * HH + hh)) * SS + sidx) * DD];
            #pragma unroll
            for (int nt = 0; nt < 8; nt++) {
                const int d = nt * 8 + t4 * 2;
                float2 rv;
                rv.x = acc[mt][nt][half * 2 + 0] + bias[hh * DD + d + 0];
                rv.y = acc[mt][nt][half * 2 + 1] + bias[hh * DD + d + 1];
                *(float2*)&dst[d] = rv;
            }
        }
    }
}

// ---------------------------------------------------------------------------
// Output projection: out = relu(g_attn @ g_wpt^T + bp)
// ---------------------------------------------------------------------------
__global__ __launch_bounds__(256) void gemm_out_kernel(
    const float* __restrict__ bp, float* __restrict__ out)
{
    extern __shared__ __align__(16) float sm[];
    const int n0 = blockIdx.x * 128;
    const int m0 = blockIdx.y * 128;

    float acc[2][8][4] = {};
    gemm_mainloop_mma(g_attn, g_wpt, m0, n0, acc, sm);

    const int lane = threadIdx.x & 31, wid = threadIdx.x >> 5;
    const int g = lane >> 2, t4 = lane & 3;
    const int wm = wid & 3, wn = wid >> 2;

    #pragma unroll
    for (int mt = 0; mt < 2; mt++) {
        #pragma unroll
        for (int half = 0; half < 2; half++) {
            const int row = m0 + wm * 32 + mt * 16 + g + half * 8;
            float* dst = &out[(size_t)row * EE + n0 + wn * 64];
            const float* bptr = &bp[n0 + wn * 64];
            #pragma unroll
            for (int nt = 0; nt < 8; nt++) {
                const int c = nt * 8 + t4 * 2;
                float2 rv;
                rv.x = fmaxf(acc[mt][nt][half * 2 + 0] + bptr[c + 0], 0.f);
                rv.y = fmaxf(acc[mt][nt][half * 2 + 1] + bptr[c + 1], 0.f);
                *(float2*)&dst[c] = rv;
            }
        }
    }
}

// ---------------------------------------------------------------------------
// Causal flash attention (fp32 SIMT). One block = 128 query rows of (b,h).
// ---------------------------------------------------------------------------
__global__ __launch_bounds__(256) void attn_kernel()
{
    extern __shared__ float smf[];
    float* Qt   = smf;
    float* KtPs = smf + 64 * 132;
    float* Vs   = smf + 64 * 132 + 128 * 132;

    const int qt = gridDim.x - 1 - blockIdx.x;
    const int h  = blockIdx.y;
    const int b  = blockIdx.z;
    const int q0 = qt * 128;

    const float* Q = g_q + ((size_t)(b * HH + h)) * SS * DD;
    const float* K = g_k + ((size_t)(b * HH + h)) * SS * DD;
    const float* V = g_v + ((size_t)(b * HH + h)) * SS * DD;

    const int tid = threadIdx.x;
    const int tx  = tid & 15;
    const int ty  = tid >> 4;

    #pragma unroll
    for (int ii = 0; ii < 32; ii++) {
        int idx = tid + ii * 256;
        int r = idx >> 6, e = idx & 63;
        Qt[e * 132 + r] = Q[(size_t)(q0 + r) * DD + e];
    }

    float o[8][4] = {};
    float mrow[8], lrow[8];
    #pragma unroll
    for (int i = 0; i < 8; i++) { mrow[i] = -1e30f; lrow[i] = 0.f; }

    int rbase[8];
    #pragma unroll
    for (int i = 0; i < 8; i++)
        rbase[i] = (ty * 4 + (i & 3) + ((i >> 2) * 64)) * 132;

    for (int kt = 0; kt <= qt; kt++) {
        __syncthreads();
        #pragma unroll
        for (int ii = 0; ii < 32; ii++) {
            int idx = tid + ii * 256;
            int c = idx >> 6, e = idx & 63;
            float kv = K[(size_t)(kt * 128 + c) * DD + e];
            float vv = V[(size_t)(kt * 128 + c) * DD + e];
            KtPs[e * 132 + c] = kv;
            Vs[c * 68 + e]    = vv;
        }
        __syncthreads();

        float s[8][8] = {};
        #pragma unroll
        for (int e = 0; e < 64; e++) {
            float a[8], bb[8];
            *(float4*)&a[0]  = *(const float4*)&Qt[e * 132 + ty * 4];
            *(float4*)&a[4]  = *(const float4*)&Qt[e * 132 + 64 + ty * 4];
            *(float4*)&bb[0] = *(const float4*)&KtPs[e * 132 + tx * 4];
            *(float4*)&bb[4] = *(const float4*)&KtPs[e * 132 + 64 + tx * 4];
            #pragma unroll
            for (int i = 0; i < 8; i++)
                #pragma unroll
                for (int j = 0; j < 8; j++)
                    s[i][j] += a[i] * bb[j];
        }

        const bool diag = (kt == qt);
        #pragma unroll
        for (int i = 0; i < 8; i++) {
            int r = ty * 4 + (i & 3) + ((i >> 2) * 64);
            #pragma unroll
            for (int j = 0; j < 8; j++) {
                int c = tx * 4 + (j & 3) + ((j >> 2) * 64);
                float sv = s[i][j] * 0.125f;
                if (diag && c > r) sv = -1e30f;
                s[i][j] = sv;
            }
        }

        #pragma unroll
        for (int i = 0; i < 8; i++) {
            float tm = s[i][0];
            #pragma unroll
            for (int j = 1; j < 8; j++) tm = fmaxf(tm, s[i][j]);
            #pragma unroll
            for (int off = 8; off >= 1; off >>= 1)
                tm = fmaxf(tm, __shfl_xor_sync(0xffffffffu, tm, off));
            float mn = fmaxf(mrow[i], tm);
            float f  = __expf(mrow[i] - mn);
            mrow[i] = mn;
            float rs = 0.f;
            #pragma unroll
            for (int j = 0; j < 8; j++) { s[i][j] = __expf(s[i][j] - mn); rs += s[i][j]; }
            #pragma unroll
            for (int off = 8; off >= 1; off >>= 1)
                rs += __shfl_xor_sync(0xffffffffu, rs, off);
            lrow[i] = lrow[i] * f + rs;
            #pragma unroll
            for (int j = 0; j < 4; j++) o[i][j] *= f;
        }

        __syncthreads();
        #pragma unroll
        for (int i = 0; i < 8; i++) {
            *(float4*)&KtPs[rbase[i] + tx * 4]      = *(float4*)&s[i][0];
            *(float4*)&KtPs[rbase[i] + 64 + tx * 4] = *(float4*)&s[i][4];
        }
        __syncthreads();

        #pragma unroll 4
        for (int c = 0; c < 128; c += 4) {
            float4 p[8];
            #pragma unroll
            for (int i = 0; i < 8; i++)
                p[i] = *(const float4*)&KtPs[rbase[i] + c];
            #pragma unroll
            for (int cc = 0; cc < 4; cc++) {
                float4 v4 = *(const float4*)&Vs[(c + cc) * 68 + tx * 4];
                #pragma unroll
                for (int i = 0; i < 8; i++) {
                    float pv = ((const float*)&p[i])[cc];
                    o[i][0] += pv * v4.x;
                    o[i][1] += pv * v4.y;
                    o[i][2] += pv * v4.z;
                    o[i][3] += pv * v4.w;
                }
            }
        }
    }

    // normalize, round to tf32 grid (out-proj consumes via tf32 mma), store
    #pragma unroll
    for (int i = 0; i < 8; i++) {
        int r = q0 + ty * 4 + (i & 3) + ((i >> 2) * 64);
        float invl = 1.0f / lrow[i];
        float4 rv = make_float4(rna_tf32(o[i][0] * invl), rna_tf32(o[i][1] * invl),
                                rna_tf32(o[i][2] * invl), rna_tf32(o[i][3] * invl));
        *(float4*)&g_attn[(((size_t)(b * SS + r)) * HH + h) * DD + tx * 4] = rv;
    }
}

// ============================ host side ============================
extern "C" void kernel_launch(void* const* d_in, const int* in_sizes, int n_in,
                              void* d_out, int out_size)
{
    const float* x  = (const float*)d_in[0];
    const float* Wq = (const float*)d_in[1];
    const float* Wk = (const float*)d_in[2];
    const float* Wv = (const float*)d_in[3];
    const float* bq = (const float*)d_in[4];
    const float* bk = (const float*)d_in[5];
    const float* bv = (const float*)d_in[6];
    const float* Wp = (const float*)d_in[7];
    const float* bp = (const float*)d_in[8];
    float* out = (float*)d_out;
    (void)in_sizes; (void)n_in; (void)out_size;

    cudaFuncSetAttribute(gemm_proj_kernel,
                         cudaFuncAttributeMaxDynamicSharedMemorySize, GSMEM_BYTES);
    cudaFuncSetAttribute(gemm_out_kernel,
                         cudaFuncAttributeMaxDynamicSharedMemorySize, GSMEM_BYTES);
    cudaFuncSetAttribute(attn_kernel,
                         cudaFuncAttributeMaxDynamicSharedMemorySize, 136192);

    round_x_kernel<<<1024, 256>>>(x);
    transpose_w_kernel<<<dim3(EE / 32, DD / 32, 48), 256>>>(Wq, Wk, Wv);
    transpose_wp_kernel<<<dim3(EE / 32, EE / 32), 256>>>(Wp);

    gemm_proj_kernel<<<dim3(3 * EE / 128, MTOT / 128), 256, GSMEM_BYTES>>>(bq, bk, bv);

    attn_kernel<<<dim3(SS / 128, HH, BB), 256, 136192>>>();

    gemm_out_kernel<<<dim3(EE / 128, MTOT / 128), 256, GSMEM_BYTES>>>(bp, out);
}

// round 7
// speedup vs baseline: 2.7652x; 1.6377x over previous
#include <cuda_runtime.h>
#include <cstdint>

// Problem shape (fixed)
#define BB 2
#define SS 2048
#define EE 1024
#define HH 16
#define DD 64
#define MTOT (BB*SS)   // 4096

// Scratch (device globals)
__device__ float g_xr[MTOT*EE];        // x rounded to tf32 grid
__device__ float g_wt[3*EE*EE];        // W{q,k,v}^T: [which][n=h*64+d][e], rna-rounded
__device__ float g_wpt[EE*EE];         // Wp^T: [n][k], rna-rounded
__device__ float g_q[BB*HH*SS*DD];     // [B,H,S,D], rna-rounded
__device__ float g_k[BB*HH*SS*DD];
__device__ float g_v[BB*HH*SS*DD];
__device__ float g_attn[BB*SS*HH*DD];  // [B,S,H*D], rna-rounded

// ============================ helpers ============================
__device__ __forceinline__ uint32_t smem_to_u32(const void* p) {
    uint32_t a;
    asm("{ .reg .u64 t; cvta.to.shared.u64 t, %1; cvt.u32.u64 %0, t; }" : "=r"(a) : "l"(p));
    return a;
}
__device__ __forceinline__ float rna_tf32(float v) {
    float r; asm("cvt.rna.tf32.f32 %0, %1;" : "=f"(r) : "f"(v)); return r;
}
__device__ __forceinline__ void ldgsts16(uint32_t s, const float* g) {
    asm volatile("cp.async.cg.shared.global [%0], [%1], 16;" :: "r"(s), "l"(g) : "memory");
}
#define CP_COMMIT() asm volatile("cp.async.commit_group;" ::: "memory")
#define CP_WAIT2()  asm volatile("cp.async.wait_group 2;" ::: "memory")

// m16n8k8 tf32 mma: D += A*B   (fragment conventions validated in R5)
__device__ __forceinline__ void mma16n8k8(float* d, const uint32_t* a, const uint32_t* b) {
    asm volatile(
        "mma.sync.aligned.m16n8k8.row.col.f32.tf32.tf32.f32 "
        "{%0,%1,%2,%3}, {%4,%5,%6,%7}, {%8,%9}, {%0,%1,%2,%3};\n"
        : "+f"(d[0]), "+f"(d[1]), "+f"(d[2]), "+f"(d[3])
        : "r"(a[0]), "r"(a[1]), "r"(a[2]), "r"(a[3]), "r"(b[0]), "r"(b[1]));
}

// ============================ prep kernels ============================
__global__ __launch_bounds__(256) void round_x_kernel(const float* __restrict__ x)
{
    int i = blockIdx.x * blockDim.x + threadIdx.x;
    const int n4 = MTOT * EE / 4;
    for (; i < n4; i += gridDim.x * blockDim.x) {
        float4 v = ((const float4*)x)[i];
        v.x = rna_tf32(v.x); v.y = rna_tf32(v.y);
        v.z = rna_tf32(v.z); v.w = rna_tf32(v.w);
        ((float4*)g_xr)[i] = v;
    }
}

__global__ __launch_bounds__(256) void transpose_w_kernel(
    const float* __restrict__ Wq, const float* __restrict__ Wk, const float* __restrict__ Wv)
{
    __shared__ float t[32][33];
    const int zc = blockIdx.z;              // 0..47
    const int which = zc >> 4, h = zc & 15;
    const float* W = ((which == 0) ? Wq : (which == 1) ? Wk : Wv) + (size_t)h * EE * DD;
    const int e0 = blockIdx.x * 32, d0 = blockIdx.y * 32;
    const int tx = threadIdx.x & 31, ty8 = threadIdx.x >> 5;
    #pragma unroll
    for (int i = 0; i < 4; i++) {
        int e = ty8 + i * 8;
        t[e][tx] = rna_tf32(W[(size_t)(e0 + e) * DD + d0 + tx]);
    }
    __syncthreads();
    float* dst = g_wt + (size_t)which * EE * EE;
    #pragma unroll
    for (int i = 0; i < 4; i++) {
        int dr = ty8 + i * 8;
        dst[(size_t)(h * DD + d0 + dr) * EE + e0 + tx] = t[tx][dr];
    }
}

__global__ __launch_bounds__(256) void transpose_wp_kernel(const float* __restrict__ Wp)
{
    __shared__ float t[32][33];
    const int k0 = blockIdx.x * 32, n0 = blockIdx.y * 32;
    const int tx = threadIdx.x & 31, ty8 = threadIdx.x >> 5;
    #pragma unroll
    for (int i = 0; i < 4; i++) {
        int k = ty8 + i * 8;
        t[k][tx] = rna_tf32(Wp[(size_t)(k0 + k) * EE + n0 + tx]);
    }
    __syncthreads();
    #pragma unroll
    for (int i = 0; i < 4; i++) {
        int nr = ty8 + i * 8;
        g_wpt[(size_t)(n0 + nr) * EE + k0 + tx] = t[tx][nr];
    }
}

// ============================ mma.sync GEMM core (as R5, passed) =============
#define PITCH   20
#define STAGE_F (2*128*PITCH)      // 5120 floats per stage
#define GSMEM_BYTES (3*STAGE_F*4)  // 61440

__device__ __forceinline__ void gemm_load_stage(
    uint32_t smem_u32, int s, const float* __restrict__ Ag, const float* __restrict__ Bg,
    int m0, int n0, int kt, int tid)
{
    const uint32_t baseA = smem_u32 + s * (STAGE_F * 4);
    const uint32_t baseB = baseA + 128 * PITCH * 4;
    #pragma unroll
    for (int i = 0; i < 2; i++) {
        int cid = tid + i * 256;
        int r = cid >> 2, c = cid & 3;
        ldgsts16(baseA + (r * PITCH + c * 4) * 4, Ag + (size_t)(m0 + r) * EE + kt * 16 + c * 4);
        ldgsts16(baseB + (r * PITCH + c * 4) * 4, Bg + (size_t)(n0 + r) * EE + kt * 16 + c * 4);
    }
    CP_COMMIT();
}

__device__ __forceinline__ void gemm_mainloop_mma(
    const float* __restrict__ Ag, const float* __restrict__ Bg,
    int m0, int n0, float acc[2][8][4], float* __restrict__ sm)
{
    const int tid  = threadIdx.x;
    const int lane = tid & 31, wid = tid >> 5;
    const int g = lane >> 2, t4 = lane & 3;
    const int wm = wid & 3, wn = wid >> 2;
    const uint32_t smem_u32 = smem_to_u32(sm);

    gemm_load_stage(smem_u32, 0, Ag, Bg, m0, n0, 0, tid);
    gemm_load_stage(smem_u32, 1, Ag, Bg, m0, n0, 1, tid);

    const int KT = EE / 16;   // 64
    for (int t = 0; t < KT; t++) {
        const int s = t % 3;
        if (t + 2 < KT) gemm_load_stage(smem_u32, (t + 2) % 3, Ag, Bg, m0, n0, t + 2, tid);
        else            CP_COMMIT();
        CP_WAIT2();
        __syncthreads();

        const float* As = sm + s * STAGE_F;
        const float* Bs = As + 128 * PITCH;
        #pragma unroll
        for (int ks = 0; ks < 16; ks += 8) {
            uint32_t af[2][4], bf[8][2];
            #pragma unroll
            for (int mt = 0; mt < 2; mt++) {
                const int r = wm * 32 + mt * 16 + g;
                af[mt][0] = __float_as_uint(As[r * PITCH + ks + t4]);
                af[mt][1] = __float_as_uint(As[(r + 8) * PITCH + ks + t4]);
                af[mt][2] = __float_as_uint(As[r * PITCH + ks + t4 + 4]);
                af[mt][3] = __float_as_uint(As[(r + 8) * PITCH + ks + t4 + 4]);
            }
            #pragma unroll
            for (int nt = 0; nt < 8; nt++) {
                const int n = wn * 64 + nt * 8 + g;
                bf[nt][0] = __float_as_uint(Bs[n * PITCH + ks + t4]);
                bf[nt][1] = __float_as_uint(Bs[n * PITCH + ks + t4 + 4]);
            }
            #pragma unroll
            for (int mt = 0; mt < 2; mt++)
                #pragma unroll
                for (int nt = 0; nt < 8; nt++)
                    mma16n8k8(acc[mt][nt], af[mt], bf[nt]);
        }
        __syncthreads();
    }
}

// ---------------------------------------------------------------------------
// QKV projection: scatter + bias into g_q/g_k/g_v (rna-rounded for attn mma).
// ---------------------------------------------------------------------------
__global__ __launch_bounds__(256) void gemm_proj_kernel(
    const float* __restrict__ bq, const float* __restrict__ bk, const float* __restrict__ bv)
{
    extern __shared__ __align__(16) float sm[];
    const int n0 = blockIdx.x * 128;
    const int m0 = blockIdx.y * 128;

    float acc[2][8][4] = {};
    gemm_mainloop_mma(g_xr, g_wt, m0, n0, acc, sm);

    const int which = n0 >> 10;
    const int h0 = (n0 & 1023) >> 6;
    const float* bias = (which == 0) ? bq : (which == 1) ? bk : bv;
    float*       outp = (which == 0) ? g_q : (which == 1) ? g_k : g_v;

    const int lane = threadIdx.x & 31, wid = threadIdx.x >> 5;
    const int g = lane >> 2, t4 = lane & 3;
    const int wm = wid & 3, wn = wid >> 2;
    const int hh = h0 + wn;

    #pragma unroll
    for (int mt = 0; mt < 2; mt++) {
        #pragma unroll
        for (int half = 0; half < 2; half++) {
            const int row = m0 + wm * 32 + mt * 16 + g + half * 8;
            const int bi = row >> 11, sidx = row & (SS - 1);
            float* dst = &outp[(((size_t)(bi * HH + hh)) * SS + sidx) * DD];
            #pragma unroll
            for (int nt = 0; nt < 8; nt++) {
                const int d = nt * 8 + t4 * 2;
                float2 rv;
                rv.x = rna_tf32(acc[mt][nt][half * 2 + 0] + bias[hh * DD + d + 0]);
                rv.y = rna_tf32(acc[mt][nt][half * 2 + 1] + bias[hh * DD + d + 1]);
                *(float2*)&dst[d] = rv;
            }
        }
    }
}

// ---------------------------------------------------------------------------
// Output projection: out = relu(g_attn @ g_wpt^T + bp)
// ---------------------------------------------------------------------------
__global__ __launch_bounds__(256) void gemm_out_kernel(
    const float* __restrict__ bp, float* __restrict__ out)
{
    extern __shared__ __align__(16) float sm[];
    const int n0 = blockIdx.x * 128;
    const int m0 = blockIdx.y * 128;

    float acc[2][8][4] = {};
    gemm_mainloop_mma(g_attn, g_wpt, m0, n0, acc, sm);

    const int lane = threadIdx.x & 31, wid = threadIdx.x >> 5;
    const int g = lane >> 2, t4 = lane & 3;
    const int wm = wid & 3, wn = wid >> 2;

    #pragma unroll
    for (int mt = 0; mt < 2; mt++) {
        #pragma unroll
        for (int half = 0; half < 2; half++) {
            const int row = m0 + wm * 32 + mt * 16 + g + half * 8;
            float* dst = &out[(size_t)row * EE + n0 + wn * 64];
            const float* bptr = &bp[n0 + wn * 64];
            #pragma unroll
            for (int nt = 0; nt < 8; nt++) {
                const int c = nt * 8 + t4 * 2;
                float2 rv;
                rv.x = fmaxf(acc[mt][nt][half * 2 + 0] + bptr[c + 0], 0.f);
                rv.y = fmaxf(acc[mt][nt][half * 2 + 1] + bptr[c + 1], 0.f);
                *(float2*)&dst[c] = rv;
            }
        }
    }
}

// ---------------------------------------------------------------------------
// Causal flash attention, tf32 mma.sync. One block = 128 q rows of one (b,h).
// 8 warps; warp w owns m-rows w*16..+16 (m16 slab), full n.
// smem (floats): Qs[128][68] @0 | Ks[128][68] @8704 | Vs[128][72] @17408 |
//                Ps[128][132] @26624 ; total 43520 floats = 174080 B.
// ---------------------------------------------------------------------------
#define ASMEM_BYTES 174080

__global__ __launch_bounds__(256, 1) void attn_mma_kernel()
{
    extern __shared__ float smf[];
    float* Qs = smf;            // [q][d]  pitch 68
    float* Ks = smf + 8704;     // [kv][d] pitch 68
    float* Vs = smf + 17408;    // [t][d]  pitch 72
    float* Ps = smf + 26624;    // [q][t]  pitch 132

    const int qt = gridDim.x - 1 - blockIdx.x;   // heavy tiles first
    const int h  = blockIdx.y;
    const int b  = blockIdx.z;
    const int q0 = qt * 128;

    const float* Q = g_q + ((size_t)(b * HH + h)) * SS * DD;
    const float* K = g_k + ((size_t)(b * HH + h)) * SS * DD;
    const float* V = g_v + ((size_t)(b * HH + h)) * SS * DD;

    const int tid = threadIdx.x;
    const int lane = tid & 31, w = tid >> 5;
    const int g = lane >> 2, t4 = lane & 3;
    const int r0l = w * 16 + g;          // local row (and +8)

    // load Q tile (coalesced, conflict-free)
    #pragma unroll
    for (int ii = 0; ii < 32; ii++) {
        int idx = tid + ii * 256;
        int r = idx >> 6, e = idx & 63;
        Qs[r * 68 + e] = Q[(size_t)(q0 + r) * DD + e];
    }

    float oacc[8][4] = {};
    float m0r = -1e30f, m1r = -1e30f, l0r = 0.f, l1r = 0.f;

    for (int kt = 0; kt <= qt; kt++) {
        __syncthreads();   // prev iter done with Ks/Vs/Ps (and Qs stores on iter 0)
        #pragma unroll
        for (int ii = 0; ii < 32; ii++) {
            int idx = tid + ii * 256;
            int c = idx >> 6, e = idx & 63;
            Ks[c * 68 + e] = K[(size_t)(kt * 128 + c) * DD + e];
            Vs[c * 72 + e] = V[(size_t)(kt * 128 + c) * DD + e];
        }
        __syncthreads();

        // ---- S = Q K^T : 16 n-tiles x 8 k-steps of m16n8k8 ----
        float sacc[16][4];
        #pragma unroll
        for (int nt = 0; nt < 16; nt++)
            #pragma unroll
            for (int j = 0; j < 4; j++) sacc[nt][j] = 0.f;

        #pragma unroll
        for (int kd = 0; kd < 8; kd++) {
            uint32_t af[4];
            af[0] = __float_as_uint(Qs[r0l * 68 + kd * 8 + t4]);
            af[1] = __float_as_uint(Qs[(r0l + 8) * 68 + kd * 8 + t4]);
            af[2] = __float_as_uint(Qs[r0l * 68 + kd * 8 + t4 + 4]);
            af[3] = __float_as_uint(Qs[(r0l + 8) * 68 + kd * 8 + t4 + 4]);
            #pragma unroll
            for (int nt = 0; nt < 16; nt++) {
                uint32_t bf[2];
                bf[0] = __float_as_uint(Ks[(nt * 8 + g) * 68 + kd * 8 + t4]);
                bf[1] = __float_as_uint(Ks[(nt * 8 + g) * 68 + kd * 8 + t4 + 4]);
                mma16n8k8(sacc[nt], af, bf);
            }
        }

        // ---- scale + causal mask ----
        const bool diag = (kt == qt);
        #pragma unroll
        for (int nt = 0; nt < 16; nt++) {
            #pragma unroll
            for (int j = 0; j < 4; j++) {
                int c  = nt * 8 + t4 * 2 + (j & 1);
                int rl = r0l + ((j >> 1) * 8);
                float sv = sacc[nt][j] * 0.125f;
                if (diag && c > rl) sv = -1e30f;
                sacc[nt][j] = sv;
            }
        }

        // ---- online softmax (rows g and g+8 of warp slab) ----
        float mx0 = -1e30f, mx1 = -1e30f;
        #pragma unroll
        for (int nt = 0; nt < 16; nt++) {
            mx0 = fmaxf(mx0, fmaxf(sacc[nt][0], sacc[nt][1]));
            mx1 = fmaxf(mx1, fmaxf(sacc[nt][2], sacc[nt][3]));
        }
        mx0 = fmaxf(mx0, __shfl_xor_sync(0xffffffffu, mx0, 1));
        mx0 = fmaxf(mx0, __shfl_xor_sync(0xffffffffu, mx0, 2));
        mx1 = fmaxf(mx1, __shfl_xor_sync(0xffffffffu, mx1, 1));
        mx1 = fmaxf(mx1, __shfl_xor_sync(0xffffffffu, mx1, 2));

        float mn0 = fmaxf(m0r, mx0), mn1 = fmaxf(m1r, mx1);
        float f0 = __expf(m0r - mn0), f1 = __expf(m1r - mn1);
        m0r = mn0; m1r = mn1;

        float s0 = 0.f, s1 = 0.f;
        #pragma unroll
        for (int nt = 0; nt < 16; nt++) {
            float p0 = __expf(sacc[nt][0] - mn0);
            float p1 = __expf(sacc[nt][1] - mn0);
            float p2 = __expf(sacc[nt][2] - mn1);
            float p3 = __expf(sacc[nt][3] - mn1);
            sacc[nt][0] = p0; sacc[nt][1] = p1; sacc[nt][2] = p2; sacc[nt][3] = p3;
            s0 += p0 + p1; s1 += p2 + p3;
        }
        s0 += __shfl_xor_sync(0xffffffffu, s0, 1);
        s0 += __shfl_xor_sync(0xffffffffu, s0, 2);
        s1 += __shfl_xor_sync(0xffffffffu, s1, 1);
        s1 += __shfl_xor_sync(0xffffffffu, s1, 2);
        l0r = l0r * f0 + s0;
        l1r = l1r * f1 + s1;

        #pragma unroll
        for (int nt = 0; nt < 8; nt++) {
            oacc[nt][0] *= f0; oacc[nt][1] *= f0;
            oacc[nt][2] *= f1; oacc[nt][3] *= f1;
        }

        // ---- write P to smem (rna-rounded: mma truncates operands) ----
        #pragma unroll
        for (int nt = 0; nt < 16; nt++) {
            float2 p01 = make_float2(rna_tf32(sacc[nt][0]), rna_tf32(sacc[nt][1]));
            float2 p23 = make_float2(rna_tf32(sacc[nt][2]), rna_tf32(sacc[nt][3]));
            *(float2*)&Ps[r0l * 132 + nt * 8 + t4 * 2]       = p01;
            *(float2*)&Ps[(r0l + 8) * 132 + nt * 8 + t4 * 2] = p23;
        }
        __syncthreads();

        // ---- O += P V : 16 k-steps x 8 n-tiles ----
        #pragma unroll
        for (int ks = 0; ks < 16; ks++) {
            uint32_t af[4];
            af[0] = __float_as_uint(Ps[r0l * 132 + ks * 8 + t4]);
            af[1] = __float_as_uint(Ps[(r0l + 8) * 132 + ks * 8 + t4]);
            af[2] = __float_as_uint(Ps[r0l * 132 + ks * 8 + t4 + 4]);
            af[3] = __float_as_uint(Ps[(r0l + 8) * 132 + ks * 8 + t4 + 4]);
            #pragma unroll
            for (int nt = 0; nt < 8; nt++) {
                uint32_t bf[2];
                bf[0] = __float_as_uint(Vs[(ks * 8 + t4) * 72 + nt * 8 + g]);
                bf[1] = __float_as_uint(Vs[(ks * 8 + t4 + 4) * 72 + nt * 8 + g]);
                mma16n8k8(oacc[nt], af, bf);
            }
        }
    }

    // epilogue: normalize, round, store concat-ready [B,S,H*D]
    const float inv0 = 1.0f / l0r, inv1 = 1.0f / l1r;
    const int gr0 = q0 + r0l, gr1 = gr0 + 8;
    float* dst0 = &g_attn[(((size_t)(b * SS + gr0)) * HH + h) * DD];
    float* dst1 = &g_attn[(((size_t)(b * SS + gr1)) * HH + h) * DD];
    #pragma unroll
    for (int nt = 0; nt < 8; nt++) {
        const int d = nt * 8 + t4 * 2;
        float2 r0v = make_float2(rna_tf32(oacc[nt][0] * inv0), rna_tf32(oacc[nt][1] * inv0));
        float2 r1v = make_float2(rna_tf32(oacc[nt][2] * inv1), rna_tf32(oacc[nt][3] * inv1));
        *(float2*)&dst0[d] = r0v;
        *(float2*)&dst1[d] = r1v;
    }
}

// ============================ host side ============================
extern "C" void kernel_launch(void* const* d_in, const int* in_sizes, int n_in,
                              void* d_out, int out_size)
{
    const float* x  = (const float*)d_in[0];
    const float* Wq = (const float*)d_in[1];
    const float* Wk = (const float*)d_in[2];
    const float* Wv = (const float*)d_in[3];
    const float* bq = (const float*)d_in[4];
    const float* bk = (const float*)d_in[5];
    const float* bv = (const float*)d_in[6];
    const float* Wp = (const float*)d_in[7];
    const float* bp = (const float*)d_in[8];
    float* out = (float*)d_out;
    (void)in_sizes; (void)n_in; (void)out_size;

    cudaFuncSetAttribute(gemm_proj_kernel,
                         cudaFuncAttributeMaxDynamicSharedMemorySize, GSMEM_BYTES);
    cudaFuncSetAttribute(gemm_out_kernel,
                         cudaFuncAttributeMaxDynamicSharedMemorySize, GSMEM_BYTES);
    cudaFuncSetAttribute(attn_mma_kernel,
                         cudaFuncAttributeMaxDynamicSharedMemorySize, ASMEM_BYTES);

    round_x_kernel<<<1024, 256>>>(x);
    transpose_w_kernel<<<dim3(EE / 32, DD / 32, 48), 256>>>(Wq, Wk, Wv);
    transpose_wp_kernel<<<dim3(EE / 32, EE / 32), 256>>>(Wp);

    gemm_proj_kernel<<<dim3(3 * EE / 128, MTOT / 128), 256, GSMEM_BYTES>>>(bq, bk, bv);

    attn_mma_kernel<<<dim3(SS / 128, HH, BB), 256, ASMEM_BYTES>>>();

    gemm_out_kernel<<<dim3(EE / 128, MTOT / 128), 256, GSMEM_BYTES>>>(bp, out);
}